// round 8
// baseline (speedup 1.0000x reference)
#include <cuda_runtime.h>
#include <cuda_bf16.h>
#include <math.h>
#include <cstdint>

#define N_NODES 20000
#define K_REL   4
#define E_EDGES 320000
#define INDIM   1024
#define HINDIM  256
#define DDIM    128
#define GATEH   128
#define TEMP_INV (1.0f/0.6f)
#define MCLAMP  20.0f
#define NBUCKET (K_REL * N_NODES)

// ---------------- fp32 scratch ----------------
__device__ float g_H[N_NODES * DDIM];
__device__ float g_Z[N_NODES * DDIM];
__device__ float g_M[N_NODES * K_REL * DDIM];
__device__ float g_gateH[N_NODES * GATEH];
__device__ float g_G[N_NODES * K_REL * GATEH];
__device__ float g_scores[N_NODES * K_REL];
__device__ float g_alpha[2 * N_NODES * K_REL];
__device__ float g_Xres[N_NODES * DDIM];
__device__ float g_hid[N_NODES * DDIM];
__device__ float g_colsum[DDIM + 1];
__device__ float g_stats[DDIM + 1];
// ---------------- bf16 hi/lo planes ----------------
__device__ __align__(16) __nv_bfloat16 g_Xh[N_NODES * INDIM];
__device__ __align__(16) __nv_bfloat16 g_Xl[N_NODES * INDIM];
__device__ __align__(16) __nv_bfloat16 g_b0h[N_NODES * HINDIM];
__device__ __align__(16) __nv_bfloat16 g_b0l[N_NODES * HINDIM];
__device__ __align__(16) __nv_bfloat16 g_b1h[N_NODES * HINDIM];
__device__ __align__(16) __nv_bfloat16 g_b1l[N_NODES * HINDIM];
__device__ __align__(16) __nv_bfloat16 g_Hh[N_NODES * DDIM];
__device__ __align__(16) __nv_bfloat16 g_Hl[N_NODES * DDIM];
__device__ __align__(16) __nv_bfloat16 g_Mh[N_NODES * K_REL * DDIM];
__device__ __align__(16) __nv_bfloat16 g_Ml[N_NODES * K_REL * DDIM];
__device__ __align__(16) __nv_bfloat16 g_W0h[INDIM * HINDIM];
__device__ __align__(16) __nv_bfloat16 g_W0l[INDIM * HINDIM];
__device__ __align__(16) __nv_bfloat16 g_W1h[HINDIM * HINDIM];
__device__ __align__(16) __nv_bfloat16 g_W1l[HINDIM * HINDIM];
__device__ __align__(16) __nv_bfloat16 g_W2h[HINDIM * DDIM];
__device__ __align__(16) __nv_bfloat16 g_W2l[HINDIM * DDIM];
__device__ __align__(16) __nv_bfloat16 g_Wmh[2][DDIM * DDIM];
__device__ __align__(16) __nv_bfloat16 g_Wml[2][DDIM * DDIM];
__device__ __align__(16) __nv_bfloat16 g_Wg1h[2][(2 * DDIM + 1) * GATEH];
__device__ __align__(16) __nv_bfloat16 g_Wg1l[2][(2 * DDIM + 1) * GATEH];
__device__ __align__(16) __nv_bfloat16 g_Wh1h[DDIM * DDIM];
__device__ __align__(16) __nv_bfloat16 g_Wh1l[DDIM * DDIM];
// CSR
__device__ int g_cnt[NBUCKET];
__device__ int g_off[NBUCKET + 1];
__device__ int g_cur[NBUCKET];
__device__ int g_ecol[K_REL * E_EDGES];
__device__ int g_bsum[256];
__device__ int g_btop[256];

// ================= helpers =================
__device__ __forceinline__ uint32_t smem_u32(const void* p) {
    uint32_t a;
    asm("{ .reg .u64 t; cvta.to.shared.u64 t, %1; cvt.u32.u64 %0, t; }" : "=r"(a) : "l"(p));
    return a;
}
__device__ __forceinline__ void ldsm_x4(uint32_t* r, uint32_t addr) {
    asm volatile("ldmatrix.sync.aligned.m8n8.x4.shared.b16 {%0,%1,%2,%3}, [%4];"
        : "=r"(r[0]), "=r"(r[1]), "=r"(r[2]), "=r"(r[3]) : "r"(addr));
}
__device__ __forceinline__ void ldsm_x4_t(uint32_t* r, uint32_t addr) {
    asm volatile("ldmatrix.sync.aligned.m8n8.x4.trans.shared.b16 {%0,%1,%2,%3}, [%4];"
        : "=r"(r[0]), "=r"(r[1]), "=r"(r[2]), "=r"(r[3]) : "r"(addr));
}
__device__ __forceinline__ void mma_bf16(float* c, const uint32_t* a, const uint32_t* b) {
    asm volatile("mma.sync.aligned.m16n8k16.row.col.f32.bf16.bf16.f32 "
        "{%0,%1,%2,%3}, {%4,%5,%6,%7}, {%8,%9}, {%0,%1,%2,%3};"
        : "+f"(c[0]), "+f"(c[1]), "+f"(c[2]), "+f"(c[3])
        : "r"(a[0]), "r"(a[1]), "r"(a[2]), "r"(a[3]), "r"(b[0]), "r"(b[1]));
}
__device__ __forceinline__ uint32_t pack2(float a, float b) {
    __nv_bfloat162 h = __floats2bfloat162_rn(a, b);
    return *reinterpret_cast<uint32_t*>(&h);
}
#define CP16(dst, src, sz) \
    asm volatile("cp.async.cg.shared.global [%0], [%1], 16, %2;" \
        :: "r"(dst), "l"(src), "r"(sz) : "memory")
#define CP_COMMIT() asm volatile("cp.async.commit_group;" ::: "memory")
#define CP_WAIT1()  asm volatile("cp.async.wait_group 1;" ::: "memory")
#define CP_WAIT0()  asm volatile("cp.async.wait_group 0;" ::: "memory")

// ================= bf16 hi/lo GEMM, cp.async pipeline =================
// C[M,N] = (Ah+Al)[M,K] @ (Bh+Bl)[K,N] via ahbh+ahbl+albh. BM=BN=128, BK=32.
#define GT 512
#define ROWB_A 80
#define ROWB_B 272
#define A_TILE (128 * ROWB_A)               // 10240 (one bf16 plane tile)
#define B_TILE (32 * ROWB_B)                // 8704
#define STAGE_B (2 * A_TILE + 2 * B_TILE)   // 37888
#define NSTAGE 3
#define GEMM_SMEM (NSTAGE * STAGE_B)        // 113664
#define B_OFF (2 * A_TILE)

template <bool RELU, bool BIAS, bool DUAL, bool WF32, bool WPL>
__global__ __launch_bounds__(GT) void mma_gemm(
    const __nv_bfloat16* __restrict__ Ah, const __nv_bfloat16* __restrict__ Al,
    const __nv_bfloat16* __restrict__ B1h, const __nv_bfloat16* __restrict__ B1l,
    const float* __restrict__ bias,
    float* __restrict__ C1, __nv_bfloat16* __restrict__ C1h, __nv_bfloat16* __restrict__ C1l,
    int M, int K, int N,
    const __nv_bfloat16* __restrict__ B2h, const __nv_bfloat16* __restrict__ B2l,
    float* __restrict__ C2)
{
    extern __shared__ __align__(1024) char smem[];
    const int tid = threadIdx.x;
    const int lane = tid & 31;
    const int wid = tid >> 5;
    const int warp_m = wid & 3;
    const int warp_n = wid >> 2;
    const int rowBase = blockIdx.y * 128;
    const int nch = K >> 5;

    const __nv_bfloat16* Bph = B1h;
    const __nv_bfloat16* Bpl = B1l;
    float* Cp = C1;
    int cb = blockIdx.x * 128;
    if (DUAL) {
        if (blockIdx.x == 1) { Bph = B2h; Bpl = B2l; Cp = C2; }
        cb = 0;
    }

    float acc[2][4][4];
#pragma unroll
    for (int i = 0; i < 2; i++)
#pragma unroll
        for (int j = 0; j < 4; j++)
#pragma unroll
            for (int q = 0; q < 4; q++) acc[i][j][q] = 0.f;

    const uint32_t sb = smem_u32(smem);
    const int aRow = warp_m * 32 + (lane & 7) + ((lane >> 3) & 1) * 8;
    const int aK   = ((lane >> 4) & 1) * 8;
    const uint32_t aBase = sb + (uint32_t)(aRow * ROWB_A + aK * 2);
    const uint32_t bBase = sb + (uint32_t)B_OFF
                         + (uint32_t)((lane & 15) * ROWB_B + (lane >> 4) * 16);

    // per-thread cp.async coordinates (fixed across chunks)
    const int ar  = tid >> 2;          // 0..127 (A row)
    const int asg = tid & 3;           // 0..3   (A 16B segment)
    const int br  = tid >> 4;          // 0..31  (B row)
    const int bsg = tid & 15;          // 0..15  (B 16B segment)
    const int gr  = rowBase + ar;
    const uint32_t dA = (uint32_t)(ar * ROWB_A + asg * 16);
    const uint32_t dB = (uint32_t)(B_OFF + br * ROWB_B + bsg * 16);
    const size_t srcAoff = (gr < M) ? ((size_t)gr * K + asg * 8) : 0;
    const int szA = (gr < M) ? 16 : 0;
    const size_t srcBoff = (size_t)br * N + cb + bsg * 8;

    auto issue = [&](int c) {
        const int k0 = c << 5;
        const uint32_t st = sb + (uint32_t)((c % NSTAGE) * STAGE_B);
        CP16(st + dA,          Ah + srcAoff + ((gr < M) ? k0 : 0), szA);
        CP16(st + dA + A_TILE, Al + srcAoff + ((gr < M) ? k0 : 0), szA);
        CP16(st + dB,          Bph + srcBoff + (size_t)k0 * N, 16);
        CP16(st + dB + B_TILE, Bpl + srcBoff + (size_t)k0 * N, 16);
    };

    issue(0); CP_COMMIT();
    issue(1); CP_COMMIT();

    for (int c = 0; c < nch; c++) {
        if (c + 1 < nch) { CP_WAIT1(); } else { CP_WAIT0(); }
        __syncthreads();
        const uint32_t stoff = (uint32_t)((c % NSTAGE) * STAGE_B);

#pragma unroll
        for (int ks = 0; ks < 2; ks++) {
            uint32_t ah[2][4], al[2][4], bh[2][4], bl[2][4];
#pragma unroll
            for (int mt = 0; mt < 2; mt++) {
                ldsm_x4(ah[mt], aBase + stoff + mt * 16 * ROWB_A + ks * 32);
                ldsm_x4(al[mt], aBase + stoff + A_TILE + mt * 16 * ROWB_A + ks * 32);
            }
#pragma unroll
            for (int nq = 0; nq < 2; nq++) {
                uint32_t ad = bBase + stoff + ks * 16 * ROWB_B
                            + (uint32_t)((warp_n * 32 + nq * 16) * 2);
                ldsm_x4_t(bh[nq], ad);
                ldsm_x4_t(bl[nq], ad + B_TILE);
            }
#pragma unroll
            for (int mt = 0; mt < 2; mt++) {
#pragma unroll
                for (int nt = 0; nt < 4; nt++) {
                    const uint32_t* bhp = &bh[nt >> 1][(nt & 1) * 2];
                    const uint32_t* blp = &bl[nt >> 1][(nt & 1) * 2];
                    mma_bf16(acc[mt][nt], ah[mt], bhp);
                    mma_bf16(acc[mt][nt], ah[mt], blp);
                    mma_bf16(acc[mt][nt], al[mt], bhp);
                }
            }
        }
        if (c + 2 < nch) { issue(c + 2); CP_COMMIT(); }
    }

    const int g = lane >> 2;
    const int tc2 = (lane & 3) * 2;
#pragma unroll
    for (int mt = 0; mt < 2; mt++) {
#pragma unroll
        for (int nt = 0; nt < 4; nt++) {
            int row0 = rowBase + warp_m * 32 + mt * 16 + g;
            int col = cb + warp_n * 32 + nt * 8 + tc2;
            float c0 = acc[mt][nt][0], c1 = acc[mt][nt][1];
            float c2 = acc[mt][nt][2], c3 = acc[mt][nt][3];
            if (BIAS) {
                float2 bb = *reinterpret_cast<const float2*>(bias + col);
                c0 += bb.x; c1 += bb.y; c2 += bb.x; c3 += bb.y;
            }
            if (RELU) {
                c0 = fmaxf(c0, 0.f); c1 = fmaxf(c1, 0.f);
                c2 = fmaxf(c2, 0.f); c3 = fmaxf(c3, 0.f);
            }
#pragma unroll
            for (int h = 0; h < 2; h++) {
                int row = row0 + h * 8;
                if (row >= M) continue;
                float v0 = h ? c2 : c0, v1 = h ? c3 : c1;
                if (WF32)
                    *reinterpret_cast<float2*>(Cp + (size_t)row * N + col) = make_float2(v0, v1);
                if (WPL) {
                    float h0 = __bfloat162float(__float2bfloat16(v0));
                    float h1 = __bfloat162float(__float2bfloat16(v1));
                    size_t o = ((size_t)row * N + col) >> 1;
                    reinterpret_cast<uint32_t*>(C1h)[o] = pack2(h0, h1);
                    reinterpret_cast<uint32_t*>(C1l)[o] = pack2(v0 - h0, v1 - h1);
                }
            }
        }
    }
}

// ================= batched fp32 -> bf16 hi/lo split =================
struct SJob { const float* src; __nv_bfloat16* hi; __nv_bfloat16* lo; int n; };
struct SJobs { SJob j[9]; };

__global__ void split_multi(SJobs jobs)
{
    SJob jb = jobs.j[blockIdx.y];
    int stride = gridDim.x * blockDim.x * 2;
    for (int i = (blockIdx.x * blockDim.x + threadIdx.x) * 2; i < jb.n; i += stride) {
        float2 v = *reinterpret_cast<const float2*>(jb.src + i);
        float h0 = __bfloat162float(__float2bfloat16(v.x));
        float h1 = __bfloat162float(__float2bfloat16(v.y));
        *reinterpret_cast<uint32_t*>(jb.hi + i) = pack2(h0, h1);
        *reinterpret_cast<uint32_t*>(jb.lo + i) = pack2(v.x - h0, v.y - h1);
    }
}

// ================= CSR build =================
#define SCB 160
#define SCT 256
#define SPT 2

__global__ void zero_int_kernel(int* p, int n) {
    int i = blockIdx.x * blockDim.x + threadIdx.x;
    if (i < n) p[i] = 0;
}
__global__ void hist_kernel(const int* __restrict__ rows, int* __restrict__ cnt) {
    int i = blockIdx.x * blockDim.x + threadIdx.x;
    if (i >= K_REL * E_EDGES) return;
    int k = i / E_EDGES;
    atomicAdd(&cnt[k * N_NODES + rows[i]], 1);
}
__global__ __launch_bounds__(SCT) void scan_part(const int* __restrict__ cnt, int* __restrict__ bsum)
{
    __shared__ int ss[SCT];
    int b = blockIdx.x, t = threadIdx.x;
    int base = b * SCT * SPT + t * SPT;
    int local = 0;
#pragma unroll
    for (int i = 0; i < SPT; i++) {
        int idx = base + i;
        if (idx < NBUCKET) local += cnt[idx];
    }
    ss[t] = local; __syncthreads();
    for (int d = SCT >> 1; d > 0; d >>= 1) {
        if (t < d) ss[t] += ss[t + d];
        __syncthreads();
    }
    if (t == 0) bsum[b] = ss[0];
}
__global__ __launch_bounds__(SCT) void scan_top(const int* __restrict__ bsum,
                                                int* __restrict__ btop, int* __restrict__ off)
{
    __shared__ int ss[SCT];
    int t = threadIdx.x;
    int v = (t < SCB) ? bsum[t] : 0;
    ss[t] = v; __syncthreads();
    for (int d = 1; d < SCT; d <<= 1) {
        int u = (t >= d) ? ss[t - d] : 0;
        __syncthreads();
        ss[t] += u;
        __syncthreads();
    }
    if (t < SCB) btop[t] = ss[t] - v;
    if (t == SCB - 1) off[NBUCKET] = ss[t];
}
__global__ __launch_bounds__(SCT) void scan_write(const int* __restrict__ cnt,
                                                  const int* __restrict__ btop,
                                                  int* __restrict__ off, int* __restrict__ cur)
{
    __shared__ int ss[SCT];
    int b = blockIdx.x, t = threadIdx.x;
    int base = b * SCT * SPT + t * SPT;
    int c[SPT];
    int local = 0;
#pragma unroll
    for (int i = 0; i < SPT; i++) {
        int idx = base + i;
        c[i] = (idx < NBUCKET) ? cnt[idx] : 0;
        local += c[i];
    }
    ss[t] = local; __syncthreads();
    for (int d = 1; d < SCT; d <<= 1) {
        int u = (t >= d) ? ss[t - d] : 0;
        __syncthreads();
        ss[t] += u;
        __syncthreads();
    }
    int run = btop[b] + ss[t] - local;
#pragma unroll
    for (int i = 0; i < SPT; i++) {
        int idx = base + i;
        if (idx < NBUCKET) { off[idx] = run; cur[idx] = run; run += c[i]; }
    }
}
__global__ void fill_kernel(const int* __restrict__ rows, const int* __restrict__ cols,
                            int* __restrict__ cur, int* __restrict__ ecol)
{
    int i = blockIdx.x * blockDim.x + threadIdx.x;
    if (i >= K_REL * E_EDGES) return;
    int k = i / E_EDGES;
    int p = atomicAdd(&cur[k * N_NODES + rows[i]], 1);
    ecol[p] = cols[i];
}

// ================= gather: M fp32 + hi/lo planes =================
__global__ void gather_kernel(const int* __restrict__ off, const int* __restrict__ ecol,
                              const float* __restrict__ Z, float* __restrict__ Mb,
                              __nv_bfloat16* __restrict__ Mh, __nv_bfloat16* __restrict__ Ml)
{
    int w = (blockIdx.x * blockDim.x + threadIdx.x) >> 5;
    int lane = threadIdx.x & 31;
    if (w >= NBUCKET) return;
    int k = w / N_NODES;
    int n = w - k * N_NODES;
    int s = off[w], t = off[w + 1];
    float4 a0 = make_float4(0.f, 0.f, 0.f, 0.f);
    float4 a1 = make_float4(0.f, 0.f, 0.f, 0.f);
    int e = s;
    for (; e + 2 <= t; e += 2) {
        int c0 = ecol[e], c1 = ecol[e + 1];
        float4 v0 = reinterpret_cast<const float4*>(Z + (size_t)c0 * DDIM)[lane];
        float4 v1 = reinterpret_cast<const float4*>(Z + (size_t)c1 * DDIM)[lane];
        a0.x += v0.x; a0.y += v0.y; a0.z += v0.z; a0.w += v0.w;
        a1.x += v1.x; a1.y += v1.y; a1.z += v1.z; a1.w += v1.w;
    }
    if (e < t) {
        int c0 = ecol[e];
        float4 v0 = reinterpret_cast<const float4*>(Z + (size_t)c0 * DDIM)[lane];
        a0.x += v0.x; a0.y += v0.y; a0.z += v0.z; a0.w += v0.w;
    }
    float4 r;
    r.x = fminf(fmaxf(a0.x + a1.x, -MCLAMP), MCLAMP);
    r.y = fminf(fmaxf(a0.y + a1.y, -MCLAMP), MCLAMP);
    r.z = fminf(fmaxf(a0.z + a1.z, -MCLAMP), MCLAMP);
    r.w = fminf(fmaxf(a0.w + a1.w, -MCLAMP), MCLAMP);
    size_t base = ((size_t)n * K_REL + k) * DDIM + lane * 4;
    reinterpret_cast<float4*>(Mb + base)[0] = r;
    float hx = __bfloat162float(__float2bfloat16(r.x));
    float hy = __bfloat162float(__float2bfloat16(r.y));
    float hz = __bfloat162float(__float2bfloat16(r.z));
    float hw = __bfloat162float(__float2bfloat16(r.w));
    reinterpret_cast<uint2*>(Mh + base)[0] = make_uint2(pack2(hx, hy), pack2(hz, hw));
    reinterpret_cast<uint2*>(Ml + base)[0] =
        make_uint2(pack2(r.x - hx, r.y - hy), pack2(r.z - hz, r.w - hw));
}

// ================= misc kernels =================
__global__ void zero_kernel(float* p, int n) {
    int i = blockIdx.x * blockDim.x + threadIdx.x;
    if (i < n) p[i] = 0.f;
}

__global__ void score_kernel(const float* __restrict__ G, const float* __restrict__ gateH,
                             const float* __restrict__ logdeg, const float* __restrict__ w_ld,
                             const float* __restrict__ bg1, const float* __restrict__ Wg2,
                             const float* __restrict__ bg2, float* __restrict__ scores)
{
    int warp = (blockIdx.x * blockDim.x + threadIdx.x) >> 5;
    int lane = threadIdx.x & 31;
    if (warp >= N_NODES * K_REL) return;
    int n = warp >> 2;
    float ld = logdeg[warp];
    float acc = 0.f;
#pragma unroll
    for (int i = 0; i < 4; i++) {
        int d = lane + i * 32;
        float v = G[(long long)warp * GATEH + d] + gateH[(long long)n * GATEH + d]
                + ld * w_ld[d] + bg1[d];
        v = fmaxf(v, 0.f);
        acc += v * Wg2[d];
    }
#pragma unroll
    for (int o = 16; o > 0; o >>= 1) acc += __shfl_xor_sync(0xFFFFFFFFu, acc, o);
    if (lane == 0) scores[warp] = acc + bg2[0];
}

__global__ void softmax_kernel(const float* __restrict__ scores, const float* __restrict__ mask,
                               float* __restrict__ alpha)
{
    int n = blockIdx.x * blockDim.x + threadIdx.x;
    if (n >= N_NODES) return;
    float s[K_REL], a[K_REL];
    float m = -1e30f;
#pragma unroll
    for (int k = 0; k < K_REL; k++) { s[k] = scores[n * K_REL + k] * TEMP_INV; m = fmaxf(m, s[k]); }
    float sum = 0.f;
#pragma unroll
    for (int k = 0; k < K_REL; k++) { a[k] = __expf(s[k] - m); sum += a[k]; }
    float inv = 1.f / sum;
    float sum2 = 0.f;
#pragma unroll
    for (int k = 0; k < K_REL; k++) { a[k] = a[k] * inv * mask[n * K_REL + k]; sum2 += a[k]; }
    float inv2 = 1.f / fmaxf(sum2, 1e-12f);
    float sum3 = 0.f;
#pragma unroll
    for (int k = 0; k < K_REL; k++) { a[k] = fmaxf(a[k] * inv2, 1e-8f); sum3 += a[k]; }
    float inv3 = 1.f / fmaxf(sum3, 1e-12f);
#pragma unroll
    for (int k = 0; k < K_REL; k++) alpha[n * K_REL + k] = a[k] * inv3;
}

#define FUSE_NPB 16
__global__ __launch_bounds__(DDIM) void fused_kernel(
    const float* __restrict__ Mb, const float* __restrict__ alpha,
    const float* __restrict__ H, float* __restrict__ Xres, float* __restrict__ colsum)
{
    int d = threadIdx.x;
    int n0 = blockIdx.x * FUSE_NPB;
    __shared__ float a[FUSE_NPB][K_REL];
    __shared__ float wsum[4];
    if (d < FUSE_NPB * K_REL)
        a[d >> 2][d & 3] = alpha[n0 * K_REL + d];
    __syncthreads();
    float csum = 0.f, qsum = 0.f;
#pragma unroll
    for (int i = 0; i < FUSE_NPB; i++) {
        int n = n0 + i;
        if (n >= N_NODES) break;
        float f = 0.f;
#pragma unroll
        for (int k = 0; k < K_REL; k++)
            f += a[i][k] * Mb[((size_t)n * K_REL + k) * DDIM + d];
        float x = f + H[(size_t)n * DDIM + d];
        Xres[(size_t)n * DDIM + d] = x;
        csum += x;
        qsum += x * x;
    }
    atomicAdd(&colsum[d], csum);
#pragma unroll
    for (int o = 16; o > 0; o >>= 1) qsum += __shfl_xor_sync(0xFFFFFFFFu, qsum, o);
    if ((d & 31) == 0) wsum[d >> 5] = qsum;
    __syncthreads();
    if (d == 0) atomicAdd(&colsum[DDIM], wsum[0] + wsum[1] + wsum[2] + wsum[3]);
}

__global__ void stats_kernel(const float* __restrict__ colsum, float* __restrict__ stats)
{
    int d = threadIdx.x;
    __shared__ float wsum[4];
    float mu = colsum[d] * (1.0f / N_NODES);
    stats[d] = mu;
    float q = mu * mu;
#pragma unroll
    for (int o = 16; o > 0; o >>= 1) q += __shfl_xor_sync(0xFFFFFFFFu, q, o);
    if ((d & 31) == 0) wsum[d >> 5] = q;
    __syncthreads();
    if (d == 0) {
        float summu2 = wsum[0] + wsum[1] + wsum[2] + wsum[3];
        float var = (colsum[DDIM] - (float)N_NODES * summu2) * (1.0f / N_NODES);
        var = fmaxf(var, 0.f);
        stats[DDIM] = 1.0f / (sqrtf(var) + 1e-6f);
    }
}

// normalize + relu; writes H fp32 and hi/lo planes (2 elems per thread)
__global__ void normalize_kernel(const float* __restrict__ Xres, const float* __restrict__ stats,
                                 float* __restrict__ H,
                                 __nv_bfloat16* __restrict__ Hh, __nv_bfloat16* __restrict__ Hl)
{
    int i = (blockIdx.x * blockDim.x + threadIdx.x) * 2;
    if (i >= N_NODES * DDIM) return;
    int d = i & (DDIM - 1);
    float inv = stats[DDIM];
    float2 x = *reinterpret_cast<const float2*>(Xres + i);
    float v0 = fmaxf((x.x - stats[d]) * inv, 0.f);
    float v1 = fmaxf((x.y - stats[d + 1]) * inv, 0.f);
    *reinterpret_cast<float2*>(H + i) = make_float2(v0, v1);
    float h0 = __bfloat162float(__float2bfloat16(v0));
    float h1 = __bfloat162float(__float2bfloat16(v1));
    reinterpret_cast<uint32_t*>(Hh)[i >> 1] = pack2(h0, h1);
    reinterpret_cast<uint32_t*>(Hl)[i >> 1] = pack2(v0 - h0, v1 - h1);
}

__global__ void logits_kernel(const float* __restrict__ hid, const float* __restrict__ Wh2,
                              const float* __restrict__ bh2, float* __restrict__ out)
{
    int warp = (blockIdx.x * blockDim.x + threadIdx.x) >> 5;
    int lane = threadIdx.x & 31;
    if (warp >= N_NODES) return;
    float acc = 0.f;
#pragma unroll
    for (int i = 0; i < 4; i++) {
        int d = lane + i * 32;
        acc += hid[(long long)warp * DDIM + d] * Wh2[d];
    }
#pragma unroll
    for (int o = 16; o > 0; o >>= 1) acc += __shfl_xor_sync(0xFFFFFFFFu, acc, o);
    if (lane == 0) out[warp] = acc + bh2[0];
}

__global__ void copy_alpha_kernel(const float* __restrict__ alpha, float* __restrict__ out,
                                  int out_size)
{
    int i = blockIdx.x * blockDim.x + threadIdx.x;
    if (i >= 2 * N_NODES * K_REL) return;
    if (N_NODES + i < out_size) out[N_NODES + i] = alpha[i];
}

// ================= host =================
extern "C" void kernel_launch(void* const* d_in, const int* in_sizes, int n_in,
                              void* d_out, int out_size)
{
    const float* X      = (const float*)d_in[0];
    const int*   rows   = (const int*)d_in[1];
    const int*   cols   = (const int*)d_in[2];
    const float* mask   = (const float*)d_in[3];
    const float* logdeg = (const float*)d_in[4];
    const float* W_in0  = (const float*)d_in[5];
    const float* b_in0  = (const float*)d_in[6];
    const float* W_in1  = (const float*)d_in[7];
    const float* b_in1  = (const float*)d_in[8];
    const float* W_in2  = (const float*)d_in[9];
    const float* b_in2  = (const float*)d_in[10];
    const float* Wmsg[2]  = {(const float*)d_in[11], (const float*)d_in[16]};
    const float* Wg1[2]   = {(const float*)d_in[12], (const float*)d_in[17]};
    const float* bg1[2]   = {(const float*)d_in[13], (const float*)d_in[18]};
    const float* Wg2[2]   = {(const float*)d_in[14], (const float*)d_in[19]};
    const float* bg2[2]   = {(const float*)d_in[15], (const float*)d_in[20]};
    const float* Wh1    = (const float*)d_in[21];
    const float* bh1    = (const float*)d_in[22];
    const float* Wh2    = (const float*)d_in[23];
    const float* bh2    = (const float*)d_in[24];
    float* out = (float*)d_out;

    float *H, *Z, *Mb, *gateH, *G, *scores, *alpha, *Xres, *hid, *colsum, *stats;
    int *cnt, *off, *cur, *ecol, *bsum, *btop;
    __nv_bfloat16 *Xh, *Xl, *b0h, *b0l, *b1h, *b1l, *Hh, *Hl, *Mh, *Ml;
    __nv_bfloat16 *W0h, *W0l, *W1h, *W1l, *W2h, *W2l, *Wmh, *Wml, *Wg1h, *Wg1l, *Wh1h, *Wh1l;
    cudaGetSymbolAddress((void**)&H,     g_H);
    cudaGetSymbolAddress((void**)&Z,     g_Z);
    cudaGetSymbolAddress((void**)&Mb,    g_M);
    cudaGetSymbolAddress((void**)&gateH, g_gateH);
    cudaGetSymbolAddress((void**)&G,     g_G);
    cudaGetSymbolAddress((void**)&scores,g_scores);
    cudaGetSymbolAddress((void**)&alpha, g_alpha);
    cudaGetSymbolAddress((void**)&Xres,  g_Xres);
    cudaGetSymbolAddress((void**)&hid,   g_hid);
    cudaGetSymbolAddress((void**)&colsum,g_colsum);
    cudaGetSymbolAddress((void**)&stats, g_stats);
    cudaGetSymbolAddress((void**)&cnt,   g_cnt);
    cudaGetSymbolAddress((void**)&off,   g_off);
    cudaGetSymbolAddress((void**)&cur,   g_cur);
    cudaGetSymbolAddress((void**)&ecol,  g_ecol);
    cudaGetSymbolAddress((void**)&bsum,  g_bsum);
    cudaGetSymbolAddress((void**)&btop,  g_btop);
    cudaGetSymbolAddress((void**)&Xh,  g_Xh);  cudaGetSymbolAddress((void**)&Xl,  g_Xl);
    cudaGetSymbolAddress((void**)&b0h, g_b0h); cudaGetSymbolAddress((void**)&b0l, g_b0l);
    cudaGetSymbolAddress((void**)&b1h, g_b1h); cudaGetSymbolAddress((void**)&b1l, g_b1l);
    cudaGetSymbolAddress((void**)&Hh,  g_Hh);  cudaGetSymbolAddress((void**)&Hl,  g_Hl);
    cudaGetSymbolAddress((void**)&Mh,  g_Mh);  cudaGetSymbolAddress((void**)&Ml,  g_Ml);
    cudaGetSymbolAddress((void**)&W0h, g_W0h); cudaGetSymbolAddress((void**)&W0l, g_W0l);
    cudaGetSymbolAddress((void**)&W1h, g_W1h); cudaGetSymbolAddress((void**)&W1l, g_W1l);
    cudaGetSymbolAddress((void**)&W2h, g_W2h); cudaGetSymbolAddress((void**)&W2l, g_W2l);
    cudaGetSymbolAddress((void**)&Wmh, g_Wmh); cudaGetSymbolAddress((void**)&Wml, g_Wml);
    cudaGetSymbolAddress((void**)&Wg1h,g_Wg1h);cudaGetSymbolAddress((void**)&Wg1l,g_Wg1l);
    cudaGetSymbolAddress((void**)&Wh1h,g_Wh1h);cudaGetSymbolAddress((void**)&Wh1l,g_Wh1l);

    cudaFuncSetAttribute(mma_gemm<true,true,false,false,true>,  cudaFuncAttributeMaxDynamicSharedMemorySize, GEMM_SMEM);
    cudaFuncSetAttribute(mma_gemm<true,true,false,true,true>,   cudaFuncAttributeMaxDynamicSharedMemorySize, GEMM_SMEM);
    cudaFuncSetAttribute(mma_gemm<false,false,true,true,false>, cudaFuncAttributeMaxDynamicSharedMemorySize, GEMM_SMEM);
    cudaFuncSetAttribute(mma_gemm<false,false,false,true,false>,cudaFuncAttributeMaxDynamicSharedMemorySize, GEMM_SMEM);
    cudaFuncSetAttribute(mma_gemm<true,true,false,true,false>,  cudaFuncAttributeMaxDynamicSharedMemorySize, GEMM_SMEM);

    const int WGSZ = (2 * DDIM + 1) * GATEH;  // whole Wg1 tensor
    SJobs sj;
    sj.j[0] = { X,       Xh,   Xl,   N_NODES * INDIM };
    sj.j[1] = { W_in0,   W0h,  W0l,  INDIM * HINDIM };
    sj.j[2] = { W_in1,   W1h,  W1l,  HINDIM * HINDIM };
    sj.j[3] = { W_in2,   W2h,  W2l,  HINDIM * DDIM };
    sj.j[4] = { Wmsg[0], Wmh,                Wml,                DDIM * DDIM };
    sj.j[5] = { Wmsg[1], Wmh + DDIM * DDIM,  Wml + DDIM * DDIM,  DDIM * DDIM };
    sj.j[6] = { Wg1[0],  Wg1h,               Wg1l,               WGSZ };
    sj.j[7] = { Wg1[1],  Wg1h + WGSZ,        Wg1l + WGSZ,        WGSZ };
    sj.j[8] = { Wh1,     Wh1h,               Wh1l,               DDIM * DDIM };

    const int MT = (N_NODES + 127) / 128;  // 157

    // 0: split everything; 1-2: CSR front; 3 (profiled): enc1
    split_multi<<<dim3(512, 9), 256>>>(sj);
    zero_int_kernel<<<(NBUCKET + 255) / 256, 256>>>(cnt, NBUCKET);
    hist_kernel<<<(K_REL * E_EDGES + 255) / 256, 256>>>(rows, cnt);

    mma_gemm<true,true,false,false,true><<<dim3(2, MT), GT, GEMM_SMEM>>>(
        Xh, Xl, W0h, W0l, b_in0, nullptr, b0h, b0l, N_NODES, INDIM, HINDIM,
        nullptr, nullptr, nullptr);

    scan_part<<<SCB, SCT>>>(cnt, bsum);
    scan_top<<<1, SCT>>>(bsum, btop, off);
    scan_write<<<SCB, SCT>>>(cnt, btop, off, cur);
    fill_kernel<<<(K_REL * E_EDGES + 255) / 256, 256>>>(rows, cols, cur, ecol);

    mma_gemm<true,true,false,false,true><<<dim3(2, MT), GT, GEMM_SMEM>>>(
        b0h, b0l, W1h, W1l, b_in1, nullptr, b1h, b1l, N_NODES, HINDIM, HINDIM,
        nullptr, nullptr, nullptr);
    mma_gemm<true,true,false,true,true><<<dim3(1, MT), GT, GEMM_SMEM>>>(
        b1h, b1l, W2h, W2l, b_in2, H, Hh, Hl, N_NODES, HINDIM, DDIM,
        nullptr, nullptr, nullptr);

    for (int b = 0; b < 2; b++) {
        mma_gemm<false,false,true,true,false><<<dim3(2, MT), GT, GEMM_SMEM>>>(
            Hh, Hl, Wmh + b * DDIM * DDIM, Wml + b * DDIM * DDIM, nullptr,
            Z, nullptr, nullptr, N_NODES, DDIM, DDIM,
            Wg1h + b * WGSZ, Wg1l + b * WGSZ, gateH);
        gather_kernel<<<(NBUCKET * 32 + 255) / 256, 256>>>(off, ecol, Z, Mb, Mh, Ml);
        mma_gemm<false,false,false,true,false><<<dim3(1, 625), GT, GEMM_SMEM>>>(
            Mh, Ml, Wg1h + b * WGSZ + DDIM * GATEH, Wg1l + b * WGSZ + DDIM * GATEH, nullptr,
            G, nullptr, nullptr, N_NODES * K_REL, DDIM, GATEH,
            nullptr, nullptr, nullptr);
        score_kernel<<<(N_NODES * K_REL * 32 + 255) / 256, 256>>>(G, gateH, logdeg,
            Wg1[b] + 2 * DDIM * GATEH, bg1[b], Wg2[b], bg2[b], scores);
        softmax_kernel<<<(N_NODES + 255) / 256, 256>>>(scores, mask, alpha + b * N_NODES * K_REL);
        zero_kernel<<<1, 256>>>(colsum, DDIM + 1);
        fused_kernel<<<(N_NODES + FUSE_NPB - 1) / FUSE_NPB, DDIM>>>(
            Mb, alpha + b * N_NODES * K_REL, H, Xres, colsum);
        stats_kernel<<<1, DDIM>>>(colsum, stats);
        normalize_kernel<<<(N_NODES * DDIM / 2 + 255) / 256, 256>>>(Xres, stats, H, Hh, Hl);
    }

    mma_gemm<true,true,false,true,false><<<dim3(1, MT), GT, GEMM_SMEM>>>(
        Hh, Hl, Wh1h, Wh1l, bh1, hid, nullptr, nullptr, N_NODES, DDIM, DDIM,
        nullptr, nullptr, nullptr);
    logits_kernel<<<(N_NODES * 32 + 255) / 256, 256>>>(hid, Wh2, bh2, out);
    copy_alpha_kernel<<<(2 * N_NODES * K_REL + 255) / 256, 256>>>(alpha, out, out_size);
}